// round 6
// baseline (speedup 1.0000x reference)
#include <cuda_runtime.h>
#include <mma.h>
#include <math.h>

using namespace nvcuda;

// Problem constants (fixed by the dataset)
#define N_ROWS 8192
#define M_ROWS 8192
#define FDIM   512
#define HDIM   512
#define NVIEW  3

// ---------------------------------------------------------------------------
// Scratch (device globals — no allocation allowed anywhere)
// ---------------------------------------------------------------------------
__device__ float g_q[(size_t)N_ROWS * HDIM];              // elu(cz@WqT), tf32-rounded
__device__ float g_k[(size_t)NVIEW * M_ROWS * HDIM];      // elu(zs_v@WkT), tf32-rounded
__device__ float g_U[(size_t)NVIEW * N_ROWS * FDIM];      // per-view unnormalized att@zv
__device__ float g_invn[(size_t)NVIEW * N_ROWS];          // per-view 1/max(||att_row||,eps)

__device__ __forceinline__ float to_tf32(float x) {
    unsigned u;
    asm("cvt.rna.tf32.f32 %0, %1;" : "=r"(u) : "f"(x));
    return __uint_as_float(u);
}

// ---------------------------------------------------------------------------
// Kernel 1: projections  P = elu(X @ W^T), stored tf32-rounded.
//   grid.y = 0: X=common_z, W=Wq -> g_q
//   grid.y = v+1: X=zs[v],  W=Wk -> g_k[v]
// CTA computes 64 rows x 512 cols. 512 threads = 16 warps in a 4x4 grid,
// each warp owns 16 rows x 128 cols (8 wmma accum tiles).
// ---------------------------------------------------------------------------
__global__ __launch_bounds__(512, 1)
void proj_kernel(const float* __restrict__ cz, const float* __restrict__ zs,
                 const float* __restrict__ Wq, const float* __restrict__ Wk)
{
    const int y = blockIdx.y;
    const float* X = (y == 0) ? cz : (zs + (size_t)(y - 1) * M_ROWS * FDIM);
    const float* W = (y == 0) ? Wq : Wk;
    float*       O = (y == 0) ? g_q : (g_k + (size_t)(y - 1) * M_ROWS * HDIM);
    const int rowBase = blockIdx.x * 64;

    extern __shared__ float sm[];
    float* X_s  = sm;               // [64][20]   (16 f-cols + pad)
    float* W_s  = X_s + 64 * 20;    // [512][20]
    float* stag = W_s + 512 * 20;   // [16][256] per-warp epilogue staging

    const int tid = threadIdx.x;
    const int wid = tid >> 5, lane = tid & 31;
    const int wm = wid & 3, wn = wid >> 2;

    wmma::fragment<wmma::accumulator, 16, 16, 8, float> acc[8];
#pragma unroll
    for (int t = 0; t < 8; ++t) wmma::fill_fragment(acc[t], 0.0f);

    for (int fc = 0; fc < 32; ++fc) {           // K = 512 in chunks of 16
        __syncthreads();
        // stage X chunk [64][16], tf32-rounded (vectorized)
        for (int i = tid; i < 64 * 4; i += 512) {
            int r = i >> 2, c = (i & 3) * 4;
            float4 v = *reinterpret_cast<const float4*>(&X[(size_t)(rowBase + r) * 512 + fc * 16 + c]);
            X_s[r * 20 + c + 0] = to_tf32(v.x);
            X_s[r * 20 + c + 1] = to_tf32(v.y);
            X_s[r * 20 + c + 2] = to_tf32(v.z);
            X_s[r * 20 + c + 3] = to_tf32(v.w);
        }
        // stage W chunk [512][16]
        for (int i = tid; i < 512 * 4; i += 512) {
            int r = i >> 2, c = (i & 3) * 4;
            float4 v = *reinterpret_cast<const float4*>(&W[(size_t)r * 512 + fc * 16 + c]);
            W_s[r * 20 + c + 0] = to_tf32(v.x);
            W_s[r * 20 + c + 1] = to_tf32(v.y);
            W_s[r * 20 + c + 2] = to_tf32(v.z);
            W_s[r * 20 + c + 3] = to_tf32(v.w);
        }
        __syncthreads();
#pragma unroll
        for (int kk = 0; kk < 2; ++kk) {
            wmma::fragment<wmma::matrix_a, 16, 16, 8, wmma::precision::tf32, wmma::row_major> a;
            wmma::load_matrix_sync(a, X_s + (wm * 16) * 20 + kk * 8, 20);
#pragma unroll
            for (int t = 0; t < 8; ++t) {
                // B(k=f, n=h) = W[h][f] -> col_major with ld = row stride of W_s
                wmma::fragment<wmma::matrix_b, 16, 16, 8, wmma::precision::tf32, wmma::col_major> b;
                wmma::load_matrix_sync(b, W_s + (wn * 128 + t * 16) * 20 + kk * 8, 20);
                wmma::mma_sync(acc[t], a, b, acc[t]);
            }
        }
    }

    // Epilogue: elu + tf32-round, via per-warp SMEM staging
    float* stw = stag + wid * 256;
#pragma unroll
    for (int t = 0; t < 8; ++t) {
        __syncwarp();
        wmma::store_matrix_sync(stw, acc[t], 16, wmma::mem_row_major);
        __syncwarp();
#pragma unroll
        for (int j = 0; j < 8; ++j) {
            int idx = lane * 8 + j;
            int r = idx >> 4, c = idx & 15;
            float x = stw[idx];
            x = (x > 0.0f) ? x : expm1f(x);
            O[(size_t)(rowBase + wm * 16 + r) * 512 + wn * 128 + t * 16 + c] = to_tf32(x);
        }
    }
}

// ---------------------------------------------------------------------------
// Kernel 2: fused attention per (row-tile, view).
//   S = q_tile @ k_v^T   (streamed over M in tiles of 64, K=H=512 chunks of 64)
//   sumsq_row += sum(S^2)   (full-precision S, before tf32 rounding)
//   U += tf32(S) @ zv_tile  (zv streamed in 16-row chunks, full F=512 width)
// Grid: (N/64, V). 512 threads = 16 warps (4x4).
// GEMM1: each warp owns one 16x16 S tile. GEMM2: warp owns 16 rows x 128 cols of U.
// ---------------------------------------------------------------------------
__global__ __launch_bounds__(512, 1)
void fused_kernel(const float* __restrict__ zs)
{
    const int v = blockIdx.y;
    const int rowBase = blockIdx.x * 64;
    const float* kv = g_k + (size_t)v * M_ROWS * HDIM;
    const float* zv = zs  + (size_t)v * M_ROWS * FDIM;

    extern __shared__ float sm[];
    float* q_s  = sm;                 // [64][520]  q tile, resident (already tf32)
    float* k_s  = q_s + 64 * 520;     // [64][72]   k chunk (64 rows x 64 h)
    float* S_s  = k_s + 64 * 72;      // [64][72]   S tile (also reused for ssq reduce)
    float* zv_s = S_s + 64 * 72;      // [16][520]  zv chunk (16 m-rows x 512 f)

    const int tid = threadIdx.x;
    const int wid = tid >> 5;
    const int wm = wid & 3, wn = wid >> 2;

    // Load resident q tile (vectorized copy; g_q already tf32-rounded)
    for (int i = tid; i < 64 * 128; i += 512) {
        int r = i >> 7, c = (i & 127) * 4;
        float4 vq = *reinterpret_cast<const float4*>(&g_q[(size_t)(rowBase + r) * 512 + c]);
        *reinterpret_cast<float4*>(&q_s[r * 520 + c]) = vq;
    }

    wmma::fragment<wmma::accumulator, 16, 16, 8, float> U[8];
#pragma unroll
    for (int t = 0; t < 8; ++t) wmma::fill_fragment(U[t], 0.0f);

    // Deterministic sumsq: thread (srow, ssub) exclusively owns 8 columns of one row.
    float myssq = 0.0f;
    const int srow = tid >> 3;   // 0..63
    const int ssub = tid & 7;    // 0..7

    for (int mt = 0; mt < 128; ++mt) {
        const int nBase = mt * 64;

        // ---- GEMM1: S = q @ k^T over H=512 in chunks of 64 ----
        wmma::fragment<wmma::accumulator, 16, 16, 8, float> Sacc;
        wmma::fill_fragment(Sacc, 0.0f);

        for (int hc = 0; hc < 8; ++hc) {
            __syncthreads();   // also orders prior-tile S_s/zv_s consumers
            for (int i = tid; i < 64 * 16; i += 512) {
                int r = i >> 4, c = (i & 15) * 4;
                float4 vk = *reinterpret_cast<const float4*>(&kv[(size_t)(nBase + r) * 512 + hc * 64 + c]);
                *reinterpret_cast<float4*>(&k_s[r * 72 + c]) = vk;
            }
            __syncthreads();
#pragma unroll
            for (int kb = 0; kb < 8; ++kb) {
                wmma::fragment<wmma::matrix_a, 16, 16, 8, wmma::precision::tf32, wmma::row_major> a;
                wmma::load_matrix_sync(a, q_s + (wm * 16) * 520 + hc * 64 + kb * 8, 520);
                // B(k=h, n=j) = k[j][h] -> col_major, ld = row stride of k_s
                wmma::fragment<wmma::matrix_b, 16, 16, 8, wmma::precision::tf32, wmma::col_major> b;
                wmma::load_matrix_sync(b, k_s + (wn * 16) * 72 + kb * 8, 72);
                wmma::mma_sync(Sacc, a, b, Sacc);
            }
        }

        // Each warp stores its exclusive 16x16 S tile
        wmma::store_matrix_sync(S_s + (wm * 16) * 72 + wn * 16, Sacc, 72, wmma::mem_row_major);
        __syncthreads();

        // sumsq (full precision) + in-place tf32 rounding for the second GEMM
#pragma unroll
        for (int j = 0; j < 8; ++j) {
            int c = ssub * 8 + j;
            float x = S_s[srow * 72 + c];
            myssq += x * x;
            S_s[srow * 72 + c] = to_tf32(x);
        }
        // (ordered before GEMM2 reads by the sync at the top of the c4 loop)

        // ---- GEMM2: U += S @ zv, zv streamed 16 m-rows at a time ----
        for (int c4 = 0; c4 < 4; ++c4) {
            __syncthreads();
            for (int i = tid; i < 16 * 128; i += 512) {
                int r = i >> 7, c = (i & 127) * 4;
                float4 vz = *reinterpret_cast<const float4*>(&zv[(size_t)(nBase + c4 * 16 + r) * 512 + c]);
                zv_s[r * 520 + c + 0] = to_tf32(vz.x);
                zv_s[r * 520 + c + 1] = to_tf32(vz.y);
                zv_s[r * 520 + c + 2] = to_tf32(vz.z);
                zv_s[r * 520 + c + 3] = to_tf32(vz.w);
            }
            __syncthreads();
#pragma unroll
            for (int kk = 0; kk < 2; ++kk) {
                wmma::fragment<wmma::matrix_a, 16, 16, 8, wmma::precision::tf32, wmma::row_major> a2;
                wmma::load_matrix_sync(a2, S_s + (wm * 16) * 72 + c4 * 16 + kk * 8, 72);
#pragma unroll
                for (int t = 0; t < 8; ++t) {
                    wmma::fragment<wmma::matrix_b, 16, 16, 8, wmma::precision::tf32, wmma::row_major> b2;
                    wmma::load_matrix_sync(b2, zv_s + (kk * 8) * 520 + wn * 128 + t * 16, 520);
                    wmma::mma_sync(U[t], a2, b2, U[t]);
                }
            }
        }
    }

    // ---- Epilogue: deterministic per-row sumsq reduction -> g_invn ----
    __syncthreads();           // all S_s readers done; reuse S_s as [512] scratch
    S_s[tid] = myssq;          // index tid == srow*8 + ssub
    __syncthreads();
    if (tid < 64) {
        float s = 0.0f;
#pragma unroll
        for (int j = 0; j < 8; ++j) s += S_s[tid * 8 + j];
        g_invn[(size_t)v * N_ROWS + rowBase + tid] = 1.0f / fmaxf(sqrtf(s), 1e-12f);
    }

    // Store unnormalized U (combine kernel applies the row scale)
    float* Uo = g_U + ((size_t)v * N_ROWS + rowBase) * FDIM;
#pragma unroll
    for (int t = 0; t < 8; ++t) {
        wmma::store_matrix_sync(Uo + (size_t)(wm * 16) * 512 + wn * 128 + t * 16,
                                U[t], 512, wmma::mem_row_major);
    }
}

// ---------------------------------------------------------------------------
// Kernel 3: out = common_z + sum_v U_v * invnorm_v   (bitwise deterministic)
// ---------------------------------------------------------------------------
__global__ void combine_kernel(const float* __restrict__ cz, float* __restrict__ out)
{
    const int i = blockIdx.x * blockDim.x + threadIdx.x;  // grid exactly covers N*F
    const int r = i >> 9;
    const size_t NF = (size_t)N_ROWS * FDIM;
    float acc = cz[i];
    acc += g_U[i]            * g_invn[r];
    acc += g_U[NF + i]       * g_invn[N_ROWS + r];
    acc += g_U[2 * NF + i]   * g_invn[2 * N_ROWS + r];
    out[i] = acc;
}

// ---------------------------------------------------------------------------
extern "C" void kernel_launch(void* const* d_in, const int* in_sizes, int n_in,
                              void* d_out, int out_size)
{
    const float* cz = (const float*)d_in[0];
    const float* zs = (const float*)d_in[1];
    const float* Wq = (const float*)d_in[2];
    const float* Wk = (const float*)d_in[3];
    float* out = (float*)d_out;

    const int smem_proj  = (64 * 20 + 512 * 20 + 16 * 256) * (int)sizeof(float);         // 62,464 B
    const int smem_fused = (64 * 520 + 64 * 72 + 64 * 72 + 16 * 520) * (int)sizeof(float); // 203,264 B

    // Idempotent; safe during graph capture (not a stream op). First (correctness)
    // call sets them for the whole process either way.
    cudaFuncSetAttribute(proj_kernel,  cudaFuncAttributeMaxDynamicSharedMemorySize, smem_proj);
    cudaFuncSetAttribute(fused_kernel, cudaFuncAttributeMaxDynamicSharedMemorySize, smem_fused);

    proj_kernel<<<dim3(128, 4), 512, smem_proj>>>(cz, zs, Wq, Wk);
    fused_kernel<<<dim3(128, 3), 512, smem_fused>>>(zs);
    combine_kernel<<<4096, 1024>>>(cz, out);
}

// round 7
// speedup vs baseline: 8.7110x; 8.7110x over previous
#include <cuda_runtime.h>
#include <mma.h>
#include <math.h>

using namespace nvcuda;

// Problem constants (fixed by the dataset)
#define N_ROWS 8192
#define M_ROWS 8192
#define FDIM   512
#define HDIM   512
#define NVIEW  3

// ---------------------------------------------------------------------------
// Scratch (device globals — no allocation allowed anywhere)
// ---------------------------------------------------------------------------
__device__ float g_q[(size_t)N_ROWS * HDIM];              // elu(cz@WqT), tf32-rounded
__device__ float g_k[(size_t)NVIEW * M_ROWS * HDIM];      // elu(zs_v@WkT), tf32-rounded
__device__ float g_GCp[(size_t)4 * HDIM * 3072];          // split-K partials of [G|C] blocks
__device__ float g_GC[(size_t)HDIM * 3072];               // B matrix: [h][v*1024 + (G:0..511 | C:512..1023)]
__device__ float g_TU[(size_t)N_ROWS * 3072];             // q @ g_GC   (T and U interleaved per view)

__device__ __forceinline__ float to_tf32(float x) {
    unsigned u;
    asm("cvt.rna.tf32.f32 %0, %1;" : "=r"(u) : "f"(x));
    return __uint_as_float(u);
}

// ---------------------------------------------------------------------------
// Kernel 1: projections  P = elu(X @ W^T), stored tf32-rounded. (UNCHANGED)
//   grid.y = 0: X=common_z, W=Wq -> g_q
//   grid.y = v+1: X=zs[v],  W=Wk -> g_k[v]
// ---------------------------------------------------------------------------
__global__ __launch_bounds__(512, 1)
void proj_kernel(const float* __restrict__ cz, const float* __restrict__ zs,
                 const float* __restrict__ Wq, const float* __restrict__ Wk)
{
    const int y = blockIdx.y;
    const float* X = (y == 0) ? cz : (zs + (size_t)(y - 1) * M_ROWS * FDIM);
    const float* W = (y == 0) ? Wq : Wk;
    float*       O = (y == 0) ? g_q : (g_k + (size_t)(y - 1) * M_ROWS * HDIM);
    const int rowBase = blockIdx.x * 64;

    extern __shared__ float sm[];
    float* X_s  = sm;               // [64][20]
    float* W_s  = X_s + 64 * 20;    // [512][20]
    float* stag = W_s + 512 * 20;   // [16][256]

    const int tid = threadIdx.x;
    const int wid = tid >> 5, lane = tid & 31;
    const int wm = wid & 3, wn = wid >> 2;

    wmma::fragment<wmma::accumulator, 16, 16, 8, float> acc[8];
#pragma unroll
    for (int t = 0; t < 8; ++t) wmma::fill_fragment(acc[t], 0.0f);

    for (int fc = 0; fc < 32; ++fc) {
        __syncthreads();
        for (int i = tid; i < 64 * 4; i += 512) {
            int r = i >> 2, c = (i & 3) * 4;
            float4 v = *reinterpret_cast<const float4*>(&X[(size_t)(rowBase + r) * 512 + fc * 16 + c]);
            X_s[r * 20 + c + 0] = to_tf32(v.x);
            X_s[r * 20 + c + 1] = to_tf32(v.y);
            X_s[r * 20 + c + 2] = to_tf32(v.z);
            X_s[r * 20 + c + 3] = to_tf32(v.w);
        }
        for (int i = tid; i < 512 * 4; i += 512) {
            int r = i >> 2, c = (i & 3) * 4;
            float4 v = *reinterpret_cast<const float4*>(&W[(size_t)r * 512 + fc * 16 + c]);
            W_s[r * 20 + c + 0] = to_tf32(v.x);
            W_s[r * 20 + c + 1] = to_tf32(v.y);
            W_s[r * 20 + c + 2] = to_tf32(v.z);
            W_s[r * 20 + c + 3] = to_tf32(v.w);
        }
        __syncthreads();
#pragma unroll
        for (int kk = 0; kk < 2; ++kk) {
            wmma::fragment<wmma::matrix_a, 16, 16, 8, wmma::precision::tf32, wmma::row_major> a;
            wmma::load_matrix_sync(a, X_s + (wm * 16) * 20 + kk * 8, 20);
#pragma unroll
            for (int t = 0; t < 8; ++t) {
                wmma::fragment<wmma::matrix_b, 16, 16, 8, wmma::precision::tf32, wmma::col_major> b;
                wmma::load_matrix_sync(b, W_s + (wn * 128 + t * 16) * 20 + kk * 8, 20);
                wmma::mma_sync(acc[t], a, b, acc[t]);
            }
        }
    }

    float* stw = stag + wid * 256;
#pragma unroll
    for (int t = 0; t < 8; ++t) {
        __syncwarp();
        wmma::store_matrix_sync(stw, acc[t], 16, wmma::mem_row_major);
        __syncwarp();
#pragma unroll
        for (int j = 0; j < 8; ++j) {
            int idx = lane * 8 + j;
            int r = idx >> 4, c = idx & 15;
            float x = stw[idx];
            x = (x > 0.0f) ? x : expm1f(x);
            O[(size_t)(rowBase + wm * 16 + r) * 512 + wn * 128 + t * 16 + c] = to_tf32(x);
        }
    }
}

// ---------------------------------------------------------------------------
// Kernel 2: gram  — per view v:  G_v = k_v^T k_v  and  C_v = k_v^T zv.
// Output layout g_GCp[ks][h][v*1024 + j]  (j<512 -> G cols, j>=512 -> C cols f=j-512)
// CTA tile 128(h) x 128(j), K(m)=2048 per split-K slice (4 slices).
// 512 threads = 16 warps (4x4), each warp 32x32 = 2x2 wmma accum tiles.
// grid = (jTile=8, hTile=4, v*4+ks = 12)
// ---------------------------------------------------------------------------
__global__ __launch_bounds__(512)
void gram_kernel(const float* __restrict__ zs)
{
    const int jTile = blockIdx.x;
    const int hTile = blockIdx.y;
    const int v  = blockIdx.z >> 2;
    const int ks = blockIdx.z & 3;
    const int hBase  = hTile * 128;
    const int jBase  = jTile * 128;
    const int mBase0 = ks * 2048;

    const float* asrc = g_k + (size_t)v * M_ROWS * HDIM;
    const bool  isG  = (jBase < 512);
    const float* bsrc = isG ? (g_k + (size_t)v * M_ROWS * HDIM)
                            : (zs  + (size_t)v * M_ROWS * FDIM);
    const int cBase = isG ? jBase : (jBase - 512);

    __shared__ float a_s[128 * 33];   // A[h][m]  (transposed on store)
    __shared__ float b_s[32 * 136];   // B[m][j]

    const int tid = threadIdx.x;
    const int wid = tid >> 5;
    const int wm = wid & 3, wn = wid >> 2;

    wmma::fragment<wmma::accumulator, 16, 16, 8, float> acc[2][2];
#pragma unroll
    for (int i = 0; i < 2; ++i)
#pragma unroll
        for (int j = 0; j < 2; ++j) wmma::fill_fragment(acc[i][j], 0.0f);

    for (int ch = 0; ch < 64; ++ch) {
        const int mBase = mBase0 + ch * 32;
        __syncthreads();
#pragma unroll
        for (int i = 0; i < 2; ++i) {
            int idx = tid + i * 512;
            int m = idx >> 5, c4 = (idx & 31) * 4;
            // A chunk: k[mBase+m][hBase + c4..+3], transposed into a_s[h][m]
            float4 va = *reinterpret_cast<const float4*>(&asrc[(size_t)(mBase + m) * 512 + hBase + c4]);
            a_s[(c4 + 0) * 33 + m] = va.x;
            a_s[(c4 + 1) * 33 + m] = va.y;
            a_s[(c4 + 2) * 33 + m] = va.z;
            a_s[(c4 + 3) * 33 + m] = va.w;
            // B chunk: bsrc[mBase+m][cBase + c4..+3]  (tf32-round; idempotent for g_k)
            float4 vb = *reinterpret_cast<const float4*>(&bsrc[(size_t)(mBase + m) * 512 + cBase + c4]);
            b_s[m * 136 + c4 + 0] = to_tf32(vb.x);
            b_s[m * 136 + c4 + 1] = to_tf32(vb.y);
            b_s[m * 136 + c4 + 2] = to_tf32(vb.z);
            b_s[m * 136 + c4 + 3] = to_tf32(vb.w);
        }
        __syncthreads();
#pragma unroll
        for (int t = 0; t < 4; ++t) {
            wmma::fragment<wmma::matrix_a, 16, 16, 8, wmma::precision::tf32, wmma::row_major> a0, a1;
            wmma::load_matrix_sync(a0, a_s + (wm * 32 + 0)  * 33 + t * 8, 33);
            wmma::load_matrix_sync(a1, a_s + (wm * 32 + 16) * 33 + t * 8, 33);
            wmma::fragment<wmma::matrix_b, 16, 16, 8, wmma::precision::tf32, wmma::row_major> b0, b1;
            wmma::load_matrix_sync(b0, b_s + (t * 8) * 136 + wn * 32 + 0,  136);
            wmma::load_matrix_sync(b1, b_s + (t * 8) * 136 + wn * 32 + 16, 136);
            wmma::mma_sync(acc[0][0], a0, b0, acc[0][0]);
            wmma::mma_sync(acc[0][1], a0, b1, acc[0][1]);
            wmma::mma_sync(acc[1][0], a1, b0, acc[1][0]);
            wmma::mma_sync(acc[1][1], a1, b1, acc[1][1]);
        }
    }

    float* op = g_GCp + ((size_t)ks * 512 + hBase + wm * 32) * 3072
                      + (size_t)(v * 1024 + jBase + wn * 32);
#pragma unroll
    for (int i = 0; i < 2; ++i)
#pragma unroll
        for (int j = 0; j < 2; ++j)
            wmma::store_matrix_sync(op + (size_t)(i * 16) * 3072 + j * 16,
                                    acc[i][j], 3072, wmma::mem_row_major);
}

// ---------------------------------------------------------------------------
// Kernel 3: reduce split-K partials, tf32-round -> g_GC  (512*3072 elements)
// ---------------------------------------------------------------------------
__global__ void gramreduce_kernel()
{
    const size_t i = ((size_t)blockIdx.x * 512 + threadIdx.x) * 4;  // 768*512 float4s
    const size_t S = (size_t)512 * 3072;
    float4 a = *reinterpret_cast<const float4*>(&g_GCp[i]);
    float4 b = *reinterpret_cast<const float4*>(&g_GCp[i + S]);
    float4 c = *reinterpret_cast<const float4*>(&g_GCp[i + 2 * S]);
    float4 d = *reinterpret_cast<const float4*>(&g_GCp[i + 3 * S]);
    float4 o;
    o.x = to_tf32(a.x + b.x + c.x + d.x);
    o.y = to_tf32(a.y + b.y + c.y + d.y);
    o.z = to_tf32(a.z + b.z + c.z + d.z);
    o.w = to_tf32(a.w + b.w + c.w + d.w);
    *reinterpret_cast<float4*>(&g_GC[i]) = o;
}

// ---------------------------------------------------------------------------
// Kernel 4: big GEMM  g_TU = g_q [8192x512] @ g_GC [512x3072]
// CTA tile 128(i) x 128(n), K=512. Same 2x2 warp-tile pattern.
// grid = (3072/128 = 24, 8192/128 = 64)
// ---------------------------------------------------------------------------
__global__ __launch_bounds__(512)
void biggemm_kernel()
{
    const int nBase = blockIdx.x * 128;
    const int iBase = blockIdx.y * 128;

    __shared__ float a_s[128 * 36];   // A[i][k]
    __shared__ float b_s[32 * 132];   // B[k][n]

    const int tid = threadIdx.x;
    const int wid = tid >> 5;
    const int wm = wid & 3, wn = wid >> 2;

    wmma::fragment<wmma::accumulator, 16, 16, 8, float> acc[2][2];
#pragma unroll
    for (int i = 0; i < 2; ++i)
#pragma unroll
        for (int j = 0; j < 2; ++j) wmma::fill_fragment(acc[i][j], 0.0f);

    for (int ch = 0; ch < 16; ++ch) {
        const int kBase = ch * 32;
        __syncthreads();
#pragma unroll
        for (int i = 0; i < 2; ++i) {
            int idx = tid + i * 512;
            {   // A: 128 rows x 8 float4
                int r = idx >> 3, c4 = (idx & 7) * 4;
                *reinterpret_cast<float4*>(&a_s[r * 36 + c4]) =
                    *reinterpret_cast<const float4*>(&g_q[(size_t)(iBase + r) * 512 + kBase + c4]);
            }
            {   // B: 32 rows x 32 float4 (already tf32-rounded)
                int h = idx >> 5, c4 = (idx & 31) * 4;
                *reinterpret_cast<float4*>(&b_s[h * 132 + c4]) =
                    *reinterpret_cast<const float4*>(&g_GC[(size_t)(kBase + h) * 3072 + nBase + c4]);
            }
        }
        __syncthreads();
#pragma unroll
        for (int t = 0; t < 4; ++t) {
            wmma::fragment<wmma::matrix_a, 16, 16, 8, wmma::precision::tf32, wmma::row_major> a0, a1;
            wmma::load_matrix_sync(a0, a_s + (wm * 32 + 0)  * 36 + t * 8, 36);
            wmma::load_matrix_sync(a1, a_s + (wm * 32 + 16) * 36 + t * 8, 36);
            wmma::fragment<wmma::matrix_b, 16, 16, 8, wmma::precision::tf32, wmma::row_major> b0, b1;
            wmma::load_matrix_sync(b0, b_s + (t * 8) * 132 + wn * 32 + 0,  132);
            wmma::load_matrix_sync(b1, b_s + (t * 8) * 132 + wn * 32 + 16, 132);
            wmma::mma_sync(acc[0][0], a0, b0, acc[0][0]);
            wmma::mma_sync(acc[0][1], a0, b1, acc[0][1]);
            wmma::mma_sync(acc[1][0], a1, b0, acc[1][0]);
            wmma::mma_sync(acc[1][1], a1, b1, acc[1][1]);
        }
    }

    float* op = g_TU + (size_t)(iBase + wm * 32) * 3072 + (size_t)(nBase + wn * 32);
#pragma unroll
    for (int i = 0; i < 2; ++i)
#pragma unroll
        for (int j = 0; j < 2; ++j)
            wmma::store_matrix_sync(op + (size_t)(i * 16) * 3072 + j * 16,
                                    acc[i][j], 3072, wmma::mem_row_major);
}

// ---------------------------------------------------------------------------
// Kernel 5: combine — per row i:
//   sumsq_v = sum_h T_v[i][h] * q[i][h]   (= q_i G_v q_i^T)
//   out[i][f] = cz[i][f] + sum_v U_v[i][f] / max(sqrt(sumsq_v), eps)
// One CTA (128 threads) per row; fixed-order tree reduce -> deterministic.
// ---------------------------------------------------------------------------
__global__ void combine_kernel(const float* __restrict__ cz, float* __restrict__ out)
{
    const int row = blockIdx.x;
    const int tid = threadIdx.x;   // 128
    __shared__ float red[3][128];
    __shared__ float inv_s[3];

    const float* Trow = g_TU + (size_t)row * 3072;
    const float* qrow = g_q  + (size_t)row * 512;

    float p0 = 0.0f, p1 = 0.0f, p2 = 0.0f;
#pragma unroll
    for (int t = 0; t < 4; ++t) {
        int h = tid + t * 128;
        float qh = qrow[h];
        p0 += Trow[h]        * qh;
        p1 += Trow[1024 + h] * qh;
        p2 += Trow[2048 + h] * qh;
    }
    red[0][tid] = p0; red[1][tid] = p1; red[2][tid] = p2;
    __syncthreads();
#pragma unroll
    for (int s = 64; s > 0; s >>= 1) {
        if (tid < s) {
            red[0][tid] += red[0][tid + s];
            red[1][tid] += red[1][tid + s];
            red[2][tid] += red[2][tid + s];
        }
        __syncthreads();
    }
    if (tid < 3) {
        float ss = fmaxf(red[tid][0], 0.0f);
        inv_s[tid] = 1.0f / fmaxf(sqrtf(ss), 1e-12f);
    }
    __syncthreads();

    const int f = tid * 4;
    float4 o = *reinterpret_cast<const float4*>(&cz[(size_t)row * 512 + f]);
#pragma unroll
    for (int v = 0; v < 3; ++v) {
        float iv = inv_s[v];
        float4 u = *reinterpret_cast<const float4*>(&Trow[v * 1024 + 512 + f]);
        o.x += u.x * iv; o.y += u.y * iv; o.z += u.z * iv; o.w += u.w * iv;
    }
    *reinterpret_cast<float4*>(&out[(size_t)row * 512 + f]) = o;
}

// ---------------------------------------------------------------------------
extern "C" void kernel_launch(void* const* d_in, const int* in_sizes, int n_in,
                              void* d_out, int out_size)
{
    const float* cz = (const float*)d_in[0];
    const float* zs = (const float*)d_in[1];
    const float* Wq = (const float*)d_in[2];
    const float* Wk = (const float*)d_in[3];
    float* out = (float*)d_out;

    const int smem_proj = (64 * 20 + 512 * 20 + 16 * 256) * (int)sizeof(float);  // 62,464 B
    cudaFuncSetAttribute(proj_kernel, cudaFuncAttributeMaxDynamicSharedMemorySize, smem_proj);

    proj_kernel<<<dim3(128, 4), 512, smem_proj>>>(cz, zs, Wq, Wk);
    gram_kernel<<<dim3(8, 4, 12), 512>>>(zs);
    gramreduce_kernel<<<768, 512>>>();
    biggemm_kernel<<<dim3(24, 64), 512>>>();
    combine_kernel<<<8192, 128>>>(cz, out);
}